// round 17
// baseline (speedup 1.0000x reference)
#include <cuda_runtime.h>
#include <cuda_fp16.h>
#include <cstdint>

// Stickbreaking attention via mma.sync (HMMA) fp16-split. B=2 H=16 S=1024 D=64.
// Chain decomposition: each q-tile's key range split into <=6-block segments
// (1 seg qb<=5, 2 segs qb 6..11, 3 segs qb 12..15). Top seg (incl diag) writes
// out + beta-product Pt; mid writes O1 + Pm; bottom writes O1 (2-seg) or O2
// (3-seg). comb: out += Pt*O1 [+ Pt*Pm*O2]. Q pre-scaled by -0.125*log2(e).

#define SEQ 1024
#define DH 64
#define BQ 64
#define BK 64
#define THREADS 128
#define NQB (SEQ / BQ)
#define FULL 0xffffffffu

#define KH_O 0
#define KL_O 8192
#define V_O  16384
#define BUFSZ 24576
#define SM_TOTAL 49152
#define NSEG 30

__device__ __align__(16) unsigned char g_kh[512 * 8192];
__device__ __align__(16) unsigned char g_kl[512 * 8192];
__device__ __align__(16) unsigned char g_vv[512 * 8192];
__device__ __align__(16) __half g_o1[32 * 1024 * 64];
__device__ __align__(16) __half g_o2[32 * 1024 * 64];
__device__ __align__(16) float g_pt[32 * 1024];
__device__ __align__(16) float g_pm[32 * 1024];

// segment table, LPT (longest-first). mode: 0=top/single 1=mid 2=bot->O1 3=bot->O2
__device__ const signed char seg_qb[NSEG] =
    {15,11,11,10, 5,15,15,14,14,14,13,13,12,10, 9, 9, 8, 4,13,12,12, 8, 7, 7, 6, 3, 6, 2, 1, 0};
__device__ const signed char seg_hi[NSEG] =
    {15,11, 5,10, 5, 9, 4,14, 9, 4,13, 4,12, 4, 9, 4, 8, 4, 8, 7, 3, 3, 7, 3, 6, 3, 2, 2, 1, 0};
__device__ const signed char seg_lo[NSEG] =
    {10, 6, 0, 5, 0, 5, 0,10, 5, 0, 9, 0, 8, 0, 5, 0, 4, 0, 5, 4, 0, 0, 4, 0, 3, 0, 0, 0, 0, 0};
__device__ const signed char seg_md[NSEG] =
    { 0, 0, 2, 0, 0, 1, 3, 0, 1, 3, 0, 3, 0, 2, 0, 2, 0, 0, 1, 1, 3, 2, 0, 2, 0, 0, 2, 0, 0, 0};

__device__ __forceinline__ uint32_t smem_u32(const void* p) {
    uint32_t a;
    asm("{ .reg .u64 t; cvta.to.shared.u64 t, %1; cvt.u32.u64 %0, t; }" : "=r"(a) : "l"(p));
    return a;
}
__device__ __forceinline__ float ex2f(float x) {
    float r; asm("ex2.approx.f32 %0, %1;" : "=f"(r) : "f"(x)); return r;
}
__device__ __forceinline__ float rcpf(float x) {
    float r; asm("rcp.approx.f32 %0, %1;" : "=f"(r) : "f"(x)); return r;
}
__device__ __forceinline__ void cp16(uint32_t dst, const void* src) {
    asm volatile("cp.async.cg.shared.global [%0], [%1], 16;" :: "r"(dst), "l"(src));
}

#define MMA(d, a, b0, b1) \
    asm volatile("mma.sync.aligned.m16n8k16.row.col.f32.f16.f16.f32 " \
        "{%0,%1,%2,%3}, {%4,%5,%6,%7}, {%8,%9}, {%0,%1,%2,%3};" \
        : "+f"((d)[0]), "+f"((d)[1]), "+f"((d)[2]), "+f"((d)[3]) \
        : "r"((a)[0]), "r"((a)[1]), "r"((a)[2]), "r"((a)[3]), "r"(b0), "r"(b1))

#define LDSM4(r, addr) \
    asm volatile("ldmatrix.sync.aligned.m8n8.x4.shared.b16 {%0,%1,%2,%3}, [%4];" \
        : "=r"((r)[0]), "=r"((r)[1]), "=r"((r)[2]), "=r"((r)[3]) : "r"(addr))

#define LDSM4T(r, addr) \
    asm volatile("ldmatrix.sync.aligned.m8n8.x4.trans.shared.b16 {%0,%1,%2,%3}, [%4];" \
        : "=r"((r)[0]), "=r"((r)[1]), "=r"((r)[2]), "=r"((r)[3]) : "r"(addr))

__device__ __forceinline__ uint32_t pack2(__half lo, __half hi) {
    __half2 t(lo, hi);
    return *reinterpret_cast<uint32_t*>(&t);
}
__device__ __forceinline__ void split2(float x, __half& h, __half& l) {
    h = __float2half_rn(x);
    l = __float2half_rn(x - __half2float(h));
}

// ---- prepass: K (hi/lo) + V (fp16) into pre-swizzled tile images ----
__global__ __launch_bounds__(THREADS)
void prep(const float* __restrict__ k, const float* __restrict__ v) {
    const int tid = threadIdx.x;
    const int bx = blockIdx.x;
    const int tilei = bx >> 2, qf = bx & 3;
    const int bh = tilei >> 4, kb = tilei & 15;
    const size_t tile = (size_t)tilei * 8192;
    const float4* gk = (const float4*)(k + ((size_t)bh * SEQ + kb * 64) * DH);
    const float4* gv = (const float4*)(v + ((size_t)bh * SEQ + kb * 64) * DH);
    #pragma unroll
    for (int i = 0; i < 2; i++) {
        int f = qf * 256 + i * THREADS + tid;
        int row = f >> 4, c4 = f & 15;
        uint32_t off = (uint32_t)(row * 128 + (((c4 >> 1) ^ (row & 7)) << 4) + (c4 & 1) * 8);
        float4 kx = gk[f];
        __half h0, h1, h2, h3, l0, l1, l2, l3;
        split2(kx.x, h0, l0); split2(kx.y, h1, l1);
        split2(kx.z, h2, l2); split2(kx.w, h3, l3);
        *(uint2*)(g_kh + tile + off) = make_uint2(pack2(h0, h1), pack2(h2, h3));
        *(uint2*)(g_kl + tile + off) = make_uint2(pack2(l0, l1), pack2(l2, l3));
        float4 vx = gv[f];
        __half v0 = __float2half_rn(vx.x), v1 = __float2half_rn(vx.y);
        __half v2 = __float2half_rn(vx.z), v3 = __float2half_rn(vx.w);
        *(uint2*)(g_vv + tile + off) = make_uint2(pack2(v0, v1), pack2(v2, v3));
    }
}

__device__ __forceinline__ void fetch_tiles(uint32_t bufb, size_t tile, int tid) {
    #pragma unroll
    for (int i = 0; i < 4; i++) {
        uint32_t c = (uint32_t)(i * 2048 + tid * 16);
        cp16(bufb + KH_O + c, g_kh + tile + c);
        cp16(bufb + KL_O + c, g_kl + tile + c);
        cp16(bufb + V_O  + c, g_vv + tile + c);
    }
    asm volatile("cp.async.commit_group;" ::: "memory");
}

__global__ __launch_bounds__(THREADS, 4)
void sb_mma(const float* __restrict__ q, float* __restrict__ out) {
    extern __shared__ __align__(16) char smem[];
    const uint32_t sb = smem_u32(smem);
    const int tid = threadIdx.x;
    const int lane = tid & 31, warp = tid >> 5;
    const int q4 = lane & 3;
    const int sel = lane >> 3, rr = lane & 7;

    const int bh = blockIdx.x & 31;
    const int t = blockIdx.x >> 5;
    const int qb = seg_qb[t];
    const int kb_hi = seg_hi[t];
    const int kb_lo = seg_lo[t];
    const int md = seg_md[t];
    const int qbase = qb * BQ;

    const float* qg = q + (size_t)bh * SEQ * DH;

    fetch_tiles(sb, (size_t)(bh * 16 + kb_hi) * 8192, tid);

    // ---- stage Q tile, pre-scaled by -0.125*log2(e), into buf1 (dead later) ----
    {
        const float NSC = -0.18033688f;
        const float4* gq = (const float4*)(qg + (size_t)qbase * DH);
        #pragma unroll
        for (int i = 0; i < 8; i++) {
            int f = i * THREADS + tid;
            int row = f >> 4, c4 = f & 15;
            float4 x = gq[f];
            __half h0, h1, h2, h3, l0, l1, l2, l3;
            split2(NSC * x.x, h0, l0); split2(NSC * x.y, h1, l1);
            split2(NSC * x.z, h2, l2); split2(NSC * x.w, h3, l3);
            uint32_t off = (uint32_t)(row * 128 + (((c4 >> 1) ^ (row & 7)) << 4) + (c4 & 1) * 8);
            *(uint2*)(smem + BUFSZ + off) = make_uint2(pack2(h0, h1), pack2(h2, h3));
            *(uint2*)(smem + BUFSZ + 8192 + off) = make_uint2(pack2(l0, l1), pack2(l2, l3));
        }
    }
    __syncthreads();

    uint32_t qh[4][4], ql[4][4];
    {
        int row = warp * 16 + (sel & 1) * 8 + rr;
        #pragma unroll
        for (int kc = 0; kc < 4; kc++) {
            int chunk = 2 * kc + (sel >> 1);
            uint32_t a = sb + BUFSZ + (uint32_t)(row * 128 + ((chunk ^ rr) << 4));
            LDSM4(qh[kc], a);
            LDSM4(ql[kc], a + 8192);
        }
    }

    float o[8][4];
    #pragma unroll
    for (int nt = 0; nt < 8; nt++) { o[nt][0] = o[nt][1] = o[nt][2] = o[nt][3] = 0.f; }
    float P0 = 1.f, P1 = 1.f;
    const int wr0 = qbase + warp * 16 + (lane >> 2);

    #pragma unroll 1
    for (int kb = kb_hi; kb >= kb_lo; --kb) {
        const int kbase = kb * BK;
        const uint32_t bsb = sb + (uint32_t)(((kb_hi - kb) & 1) ? BUFSZ : 0);

        asm volatile("cp.async.wait_group 0;" ::: "memory");
        __syncthreads();

        if (kb > kb_lo)
            fetch_tiles(sb + (uint32_t)(((kb_hi - kb) & 1) ? 0 : BUFSZ),
                        (size_t)(bh * 16 + kb - 1) * 8192, tid);

        // ---- QK^T: D = (-x2)[16 x 64], 3 split passes ----
        float d[8][4];
        #pragma unroll
        for (int nt = 0; nt < 8; nt++) { d[nt][0] = d[nt][1] = d[nt][2] = d[nt][3] = 0.f; }

        #pragma unroll
        for (int kc = 0; kc < 4; kc++) {
            uint32_t kf[16];
            const int keyl = (sel >> 1) * 8 + rr;
            const int chunk = 2 * kc + (sel & 1);
            #pragma unroll
            for (int p = 0; p < 4; p++) {
                uint32_t a = bsb + KH_O + (uint32_t)((p * 16 + keyl) * 128 + ((chunk ^ rr) << 4));
                LDSM4(&kf[p * 4], a);
            }
            #pragma unroll
            for (int nt = 0; nt < 8; nt++) MMA(d[nt], qh[kc], kf[nt * 2], kf[nt * 2 + 1]);
            #pragma unroll
            for (int nt = 0; nt < 8; nt++) MMA(d[nt], ql[kc], kf[nt * 2], kf[nt * 2 + 1]);
            #pragma unroll
            for (int p = 0; p < 4; p++) {
                uint32_t a = bsb + KL_O + (uint32_t)((p * 16 + keyl) * 128 + ((chunk ^ rr) << 4));
                LDSM4(&kf[p * 4], a);
            }
            #pragma unroll
            for (int nt = 0; nt < 8; nt++) MMA(d[nt], qh[kc], kf[nt * 2], kf[nt * 2 + 1]);
        }

        // ---- interleaved scan + PV, kc descending ----
        const bool diag = (kb == qb);
        #pragma unroll
        for (int kc = 3; kc >= 0; --kc) {
            uint32_t vf[16];
            const int keyv = kc * 16 + (sel & 1) * 8 + rr;
            #pragma unroll
            for (int p = 0; p < 4; p++) {
                int chunk = 2 * p + (sel >> 1);
                uint32_t a = bsb + V_O + (uint32_t)(keyv * 128 + ((chunk ^ rr) << 4));
                LDSM4T(&vf[p * 4], a);
            }

            uint32_t wf[4];
            #pragma unroll
            for (int nt = 2 * kc + 1; nt >= 2 * kc; --nt) {
                const int keyA = kbase + nt * 8 + 2 * q4;
                #pragma unroll
                for (int rs = 0; rs < 2; rs++) {
                    float ta = ex2f(d[nt][rs * 2 + 0]);   // d = -x2 (Q pre-scaled)
                    float tb = ex2f(d[nt][rs * 2 + 1]);
                    float za = rcpf(1.f + ta), zb = rcpf(1.f + tb);
                    float ba = 1.f - za, bb = 1.f - zb;
                    if (diag) {
                        const int rowg = wr0 + rs * 8;
                        if (keyA > rowg)     { za = 0.f; ba = 1.f; }
                        if (keyA + 1 > rowg) { zb = 0.f; bb = 1.f; }
                    }
                    float pp = ba * bb;
                    float u = pp;
                    float t1 = __shfl_down_sync(FULL, u, 1, 4);
                    u = (q4 < 3) ? u * t1 : u;
                    float t2 = __shfl_down_sync(FULL, u, 2, 4);
                    u = (q4 < 2) ? u * t2 : u;
                    float ue = __shfl_down_sync(FULL, u, 1, 4);
                    ue = (q4 < 3) ? ue : 1.f;
                    float tot = __shfl_sync(FULL, u, 0, 4);
                    float& P = rs ? P1 : P0;
                    float R  = P * ue;
                    float Rb = bb * R;
                    float wb = zb * Rb;
                    float wa = za * ba * Rb;
                    P *= tot;
                    wf[(nt & 1) * 2 + rs] =
                        pack2(__float2half_rn(wa), __float2half_rn(wb));
                }
            }

            #pragma unroll
            for (int nt = 0; nt < 8; nt++) MMA(o[nt], wf, vf[nt * 2], vf[nt * 2 + 1]);
        }
    }

    // ---- write results by mode ----
    if (md == 0) {
        float* og = out + (size_t)bh * SEQ * DH;
        float* r0p = og + (size_t)wr0 * DH;
        float* r1p = og + (size_t)(wr0 + 8) * DH;
        #pragma unroll
        for (int nt = 0; nt < 8; nt++) {
            *(float2*)(r0p + nt * 8 + 2 * q4) = make_float2(o[nt][0], o[nt][1]);
            *(float2*)(r1p + nt * 8 + 2 * q4) = make_float2(o[nt][2], o[nt][3]);
        }
        if (qb >= 6 && q4 == 0) {
            g_pt[bh * 1024 + wr0] = P0;
            g_pt[bh * 1024 + wr0 + 8] = P1;
        }
    } else {
        __half* base = (md == 3) ? g_o2 : g_o1;
        __half* r0p = base + ((size_t)bh * 1024 + wr0) * DH;
        __half* r1p = base + ((size_t)bh * 1024 + wr0 + 8) * DH;
        #pragma unroll
        for (int nt = 0; nt < 8; nt++) {
            *(__half2*)(r0p + nt * 8 + 2 * q4) = __floats2half2_rn(o[nt][0], o[nt][1]);
            *(__half2*)(r1p + nt * 8 + 2 * q4) = __floats2half2_rn(o[nt][2], o[nt][3]);
        }
        if (md == 1 && q4 == 0) {
            g_pm[bh * 1024 + wr0] = P0;
            g_pm[bh * 1024 + wr0 + 8] = P1;
        }
    }
}

// ---- combine: rows 384..1023: out += Pt*O1 (+ Pt*Pm*O2 for qb>=12) ----
__global__ __launch_bounds__(THREADS)
void comb(float* __restrict__ out) {
    const int x = blockIdx.x;            // bh*80 + rowgroup(8 rows)
    const int bh = x / 80, rg = x % 80;
    const int tid = threadIdx.x;
    const int rl = tid >> 4, c = tid & 15;
    const int row = 384 + rg * 8 + rl;          // 384..1023
    const float pt = g_pt[bh * 1024 + row];
    const __half2* o1 = (const __half2*)(g_o1 + ((size_t)bh * 1024 + row) * DH + c * 4);
    float2 fa = __half22float2(o1[0]);
    float2 fb = __half22float2(o1[1]);
    float4 add;
    add.x = pt * fa.x; add.y = pt * fa.y; add.z = pt * fb.x; add.w = pt * fb.y;
    if (row >= 768) {
        const float pm = pt * g_pm[bh * 1024 + row];
        const __half2* o2 = (const __half2*)(g_o2 + ((size_t)bh * 1024 + row) * DH + c * 4);
        float2 ga = __half22float2(o2[0]);
        float2 gb = __half22float2(o2[1]);
        add.x += pm * ga.x; add.y += pm * ga.y;
        add.z += pm * gb.x; add.w += pm * gb.y;
    }
    float4* op = (float4*)(out + ((size_t)bh * SEQ + row) * DH) + c;
    float4 ov = *op;
    ov.x += add.x; ov.y += add.y; ov.z += add.z; ov.w += add.w;
    *op = ov;
}

extern "C" void kernel_launch(void* const* d_in, const int* in_sizes, int n_in,
                              void* d_out, int out_size) {
    const float* q = (const float*)d_in[0];
    const float* k = (const float*)d_in[1];
    const float* v = (const float*)d_in[2];
    float* out = (float*)d_out;
    (void)in_sizes; (void)n_in; (void)out_size;

    prep<<<2048, THREADS>>>(k, v);

    cudaFuncSetAttribute(sb_mma, cudaFuncAttributeMaxDynamicSharedMemorySize, SM_TOTAL);
    sb_mma<<<NSEG * 32, THREADS, SM_TOTAL>>>(q, out);   // 960 CTAs, LPT order

    comb<<<32 * 80, THREADS>>>(out);
}